// round 7
// baseline (speedup 1.0000x reference)
#include <cuda_runtime.h>
#include <cstdint>
#include <math.h>

#define E_ 8
#define C_ 1024
#define H_ 2048
#define I_ 5632

// inter scratch [E, C, I] fp32 (176 MB)
__device__ float g_scratch[(size_t)E_ * C_ * I_];

constexpr int LDSW = 36;     // padded row stride (floats)
constexpr int THREADS = 128; // 4 warps
constexpr int BK = 32;
constexpr int S = 3;         // pipeline stages, 1 barrier per kt

__device__ __forceinline__ uint32_t f2tf32(float x) {
    uint32_t y;
    asm("cvt.rna.tf32.f32 %0, %1;" : "=r"(y) : "f"(x));
    return y;
}
__device__ __forceinline__ void mma_tf32(float (&c)[4], const uint32_t (&a)[4],
                                         const uint32_t (&b)[2]) {
    asm volatile(
        "mma.sync.aligned.m16n8k8.row.col.f32.tf32.tf32.f32 "
        "{%0,%1,%2,%3}, {%4,%5,%6,%7}, {%8,%9}, {%0,%1,%2,%3};\n"
        : "+f"(c[0]), "+f"(c[1]), "+f"(c[2]), "+f"(c[3])
        : "r"(a[0]), "r"(a[1]), "r"(a[2]), "r"(a[3]), "r"(b[0]), "r"(b[1]));
}
__device__ __forceinline__ void cp_async16(void* smem_ptr, const void* gmem_ptr) {
    uint32_t s = (uint32_t)__cvta_generic_to_shared(smem_ptr);
    asm volatile("cp.async.cg.shared.global [%0], [%1], 16;\n" ::"r"(s), "l"(gmem_ptr));
}
__device__ __forceinline__ void cp_commit() { asm volatile("cp.async.commit_group;\n"); }
template <int N>
__device__ __forceinline__ void cp_wait() {
    asm volatile("cp.async.wait_group %0;\n" ::"n"(N));
}
__device__ __forceinline__ float silu(float x) { return x / (1.f + __expf(-x)); }

// ============ fused gate+up: inter = silu(X·gateᵀ) * (X·upᵀ) ============
// CTA tile: 128 rows (C) x 64 cols (I), computing BOTH G and U.
// Warps 2x2; warp tile 64x32 for each matrix. aux:HMMA ratio 1.0 (as R6).
constexpr int F_ROWS = 128 + 64 + 64;                 // A + Bg + Bu rows per stage
constexpr int F_STAGE = F_ROWS * LDSW;                // 9216 floats
constexpr int F_SMEM = S * F_STAGE * 4;               // 110592 B -> 2 CTAs/SM

__global__ void __launch_bounds__(THREADS)
gateup_fused(const float* __restrict__ A, const float* __restrict__ Bg,
             const float* __restrict__ Bu, float* __restrict__ Cout) {
    extern __shared__ float smem[];
    constexpr int K = H_, N = I_, KT = K / BK;
    const int e = blockIdx.z;
    const int bm = blockIdx.y, bn = blockIdx.x;
    const int tid = threadIdx.x;
    const int warp = tid >> 5, lane = tid & 31;
    const int wm = warp >> 1, wn = warp & 1;
    const int gid = lane >> 2, tig = lane & 3;

    const int lrow = tid >> 3;          // 0..15
    const int lcol = (tid & 7) * 4;

    const float* Ag  = A  + (size_t)e * C_ * K + (size_t)(bm * 128 + lrow) * K + lcol;
    const float* Bgg = Bg + (size_t)e * I_ * K + (size_t)(bn * 64 + lrow) * K + lcol;
    const float* Bug = Bu + (size_t)e * I_ * K + (size_t)(bn * 64 + lrow) * K + lcol;

    float accg[4][4][4], accu[4][4][4];
#pragma unroll
    for (int mt = 0; mt < 4; mt++)
#pragma unroll
        for (int nt = 0; nt < 4; nt++)
#pragma unroll
            for (int r = 0; r < 4; r++) { accg[mt][nt][r] = 0.f; accu[mt][nt][r] = 0.f; }

    // stage loader: A rows [0,128), Bg rows [128,192), Bu rows [192,256)
    auto load_stage = [&](int kt) {
        float* st = smem + (kt % S) * F_STAGE;
        const size_t ko = (size_t)kt * BK;
#pragma unroll
        for (int i = 0; i < 8; i++)
            cp_async16(&st[(lrow + i * 16) * LDSW + lcol], Ag + (size_t)(i * 16) * K + ko);
#pragma unroll
        for (int i = 0; i < 4; i++)
            cp_async16(&st[(128 + lrow + i * 16) * LDSW + lcol], Bgg + (size_t)(i * 16) * K + ko);
#pragma unroll
        for (int i = 0; i < 4; i++)
            cp_async16(&st[(192 + lrow + i * 16) * LDSW + lcol], Bug + (size_t)(i * 16) * K + ko);
    };

    load_stage(0); cp_commit();
    load_stage(1); cp_commit();

    for (int kt = 0; kt < KT; ++kt) {
        cp_wait<1>();
        __syncthreads();                 // stage kt visible; slot (kt-1)%S free
        if (kt + 2 < KT) load_stage(kt + 2);
        cp_commit();

        const float* as = smem + (kt % S) * F_STAGE;
        const float* bgs = as + 128 * LDSW;
        const float* bus = as + 192 * LDSW;

#pragma unroll
        for (int k8 = 0; k8 < BK / 8; k8++) {
            const int kc = k8 * 8;
            uint32_t afr[4][4], gfr[4][2], ufr[4][2];
#pragma unroll
            for (int mt = 0; mt < 4; mt++) {
                const int r = wm * 64 + mt * 16 + gid;
                afr[mt][0] = f2tf32(as[r * LDSW + kc + tig]);
                afr[mt][1] = f2tf32(as[(r + 8) * LDSW + kc + tig]);
                afr[mt][2] = f2tf32(as[r * LDSW + kc + tig + 4]);
                afr[mt][3] = f2tf32(as[(r + 8) * LDSW + kc + tig + 4]);
            }
#pragma unroll
            for (int nt = 0; nt < 4; nt++) {
                const int c = wn * 32 + nt * 8 + gid;
                gfr[nt][0] = f2tf32(bgs[c * LDSW + kc + tig]);
                gfr[nt][1] = f2tf32(bgs[c * LDSW + kc + tig + 4]);
                ufr[nt][0] = f2tf32(bus[c * LDSW + kc + tig]);
                ufr[nt][1] = f2tf32(bus[c * LDSW + kc + tig + 4]);
            }
#pragma unroll
            for (int mt = 0; mt < 4; mt++)
#pragma unroll
                for (int nt = 0; nt < 4; nt++) {
                    mma_tf32(accg[mt][nt], afr[mt], gfr[nt]);
                    mma_tf32(accu[mt][nt], afr[mt], ufr[nt]);
                }
        }
    }

    const size_t base = (size_t)e * C_ * N;
#pragma unroll
    for (int mt = 0; mt < 4; mt++) {
#pragma unroll
        for (int nt = 0; nt < 4; nt++) {
            const int row0 = bm * 128 + wm * 64 + mt * 16 + gid;
            const int col = bn * 64 + wn * 32 + nt * 8 + tig * 2;
            const size_t i0 = base + (size_t)row0 * N + col;
            const size_t i1 = base + (size_t)(row0 + 8) * N + col;
            *reinterpret_cast<float2*>(Cout + i0) =
                make_float2(silu(accg[mt][nt][0]) * accu[mt][nt][0],
                            silu(accg[mt][nt][1]) * accu[mt][nt][1]);
            *reinterpret_cast<float2*>(Cout + i1) =
                make_float2(silu(accg[mt][nt][2]) * accu[mt][nt][2],
                            silu(accg[mt][nt][3]) * accu[mt][nt][3]);
        }
    }
}

// ============ down GEMM: out = inter · downᵀ (R6 config + S=3/1-sync) ============
constexpr int D_STAGE = 256 * LDSW;                  // (128+128) rows
constexpr int D_SMEM = S * D_STAGE * 4;              // 110592 B

__global__ void __launch_bounds__(THREADS)
down_gemm(const float* __restrict__ A, const float* __restrict__ B,
          float* __restrict__ Cout) {
    extern __shared__ float smem[];
    constexpr int K = I_, N = H_, KT = K / BK;
    const int e = blockIdx.z;
    const int bm = blockIdx.y, bn = blockIdx.x;
    const int tid = threadIdx.x;
    const int warp = tid >> 5, lane = tid & 31;
    const int wm = warp >> 1, wn = warp & 1;
    const int gid = lane >> 2, tig = lane & 3;

    const int lrow = tid >> 3;
    const int lcol = (tid & 7) * 4;

    const float* Ag = A + (size_t)e * C_ * K + (size_t)(bm * 128 + lrow) * K + lcol;
    const float* Bg = B + (size_t)e * H_ * K + (size_t)(bn * 128 + lrow) * K + lcol;

    float acc[4][8][4];
#pragma unroll
    for (int mt = 0; mt < 4; mt++)
#pragma unroll
        for (int nt = 0; nt < 8; nt++)
#pragma unroll
            for (int r = 0; r < 4; r++) acc[mt][nt][r] = 0.f;

    auto load_stage = [&](int kt) {
        float* st = smem + (kt % S) * D_STAGE;
        const size_t ko = (size_t)kt * BK;
#pragma unroll
        for (int i = 0; i < 8; i++) {
            cp_async16(&st[(lrow + i * 16) * LDSW + lcol], Ag + (size_t)(i * 16) * K + ko);
            cp_async16(&st[(128 + lrow + i * 16) * LDSW + lcol], Bg + (size_t)(i * 16) * K + ko);
        }
    };

    load_stage(0); cp_commit();
    load_stage(1); cp_commit();

    for (int kt = 0; kt < KT; ++kt) {
        cp_wait<1>();
        __syncthreads();
        if (kt + 2 < KT) load_stage(kt + 2);
        cp_commit();

        const float* as = smem + (kt % S) * D_STAGE;
        const float* bs = as + 128 * LDSW;

#pragma unroll
        for (int k8 = 0; k8 < BK / 8; k8++) {
            const int kc = k8 * 8;
            uint32_t afr[4][4], bfr[8][2];
#pragma unroll
            for (int mt = 0; mt < 4; mt++) {
                const int r = wm * 64 + mt * 16 + gid;
                afr[mt][0] = f2tf32(as[r * LDSW + kc + tig]);
                afr[mt][1] = f2tf32(as[(r + 8) * LDSW + kc + tig]);
                afr[mt][2] = f2tf32(as[r * LDSW + kc + tig + 4]);
                afr[mt][3] = f2tf32(as[(r + 8) * LDSW + kc + tig + 4]);
            }
#pragma unroll
            for (int nt = 0; nt < 8; nt++) {
                const int c = wn * 64 + nt * 8 + gid;
                bfr[nt][0] = f2tf32(bs[c * LDSW + kc + tig]);
                bfr[nt][1] = f2tf32(bs[c * LDSW + kc + tig + 4]);
            }
#pragma unroll
            for (int mt = 0; mt < 4; mt++)
#pragma unroll
                for (int nt = 0; nt < 8; nt++) mma_tf32(acc[mt][nt], afr[mt], bfr[nt]);
        }
    }

    const size_t base = (size_t)e * C_ * N;
#pragma unroll
    for (int mt = 0; mt < 4; mt++) {
#pragma unroll
        for (int nt = 0; nt < 8; nt++) {
            const int row0 = bm * 128 + wm * 64 + mt * 16 + gid;
            const int col = bn * 128 + wn * 64 + nt * 8 + tig * 2;
            const size_t i0 = base + (size_t)row0 * N + col;
            const size_t i1 = base + (size_t)(row0 + 8) * N + col;
            *reinterpret_cast<float2*>(Cout + i0) = make_float2(acc[mt][nt][0], acc[mt][nt][1]);
            *reinterpret_cast<float2*>(Cout + i1) = make_float2(acc[mt][nt][2], acc[mt][nt][3]);
        }
    }
}

extern "C" void kernel_launch(void* const* d_in, const int* in_sizes, int n_in,
                              void* d_out, int out_size) {
    const float* x    = (const float*)d_in[0];  // [E, C, H]
    const float* gate = (const float*)d_in[1];  // [E, I, H]
    const float* up   = (const float*)d_in[2];  // [E, I, H]
    const float* down = (const float*)d_in[3];  // [E, H, I]
    float* out = (float*)d_out;                 // [E, C, H]

    float* scratch = nullptr;
    cudaGetSymbolAddress((void**)&scratch, g_scratch);

    cudaFuncSetAttribute(gateup_fused, cudaFuncAttributeMaxDynamicSharedMemorySize, F_SMEM);
    cudaFuncSetAttribute(down_gemm, cudaFuncAttributeMaxDynamicSharedMemorySize, D_SMEM);

    // 1) inter = silu(X·gateᵀ) * (X·upᵀ) -> scratch [E, C, I]
    gateup_fused<<<dim3(I_ / 64, C_ / 128, E_), THREADS, F_SMEM>>>(x, gate, up, scratch);
    // 2) out = inter · downᵀ  [E, C, H]
    down_gemm<<<dim3(H_ / 128, C_ / 128, E_), THREADS, D_SMEM>>>(scratch, down, out);
}

// round 8
// speedup vs baseline: 1.0392x; 1.0392x over previous
#include <cuda_runtime.h>
#include <cstdint>
#include <math.h>

#define E_ 8
#define C_ 1024
#define H_ 2048
#define I_ 5632

// inter/gate scratch [E, C, I] fp32 (176 MB)
__device__ float g_scratch[(size_t)E_ * C_ * I_];

constexpr int BM = 128, BN = 128, BK = 32;
constexpr int LDSW = 36;                      // padded row stride (floats)
constexpr int STAGE_F = (BM + BN) * LDSW;     // 9216 floats per stage
constexpr int SMEM_BYTES = 2 * STAGE_F * 4;   // 73728 B -> 3 CTAs/SM
constexpr int THREADS = 128;                  // 4 warps, warp tile 64x64

__device__ __forceinline__ uint32_t f2tf32(float x) {
    uint32_t y;
    asm("cvt.rna.tf32.f32 %0, %1;" : "=r"(y) : "f"(x));
    return y;
}
__device__ __forceinline__ void mma_tf32(float (&c)[4], const uint32_t (&a)[4],
                                         const uint32_t (&b)[2]) {
    asm volatile(
        "mma.sync.aligned.m16n8k8.row.col.f32.tf32.tf32.f32 "
        "{%0,%1,%2,%3}, {%4,%5,%6,%7}, {%8,%9}, {%0,%1,%2,%3};\n"
        : "+f"(c[0]), "+f"(c[1]), "+f"(c[2]), "+f"(c[3])
        : "r"(a[0]), "r"(a[1]), "r"(a[2]), "r"(a[3]), "r"(b[0]), "r"(b[1]));
}
__device__ __forceinline__ void cp_async16(void* smem_ptr, const void* gmem_ptr) {
    uint32_t s = (uint32_t)__cvta_generic_to_shared(smem_ptr);
    asm volatile("cp.async.cg.shared.global [%0], [%1], 16;\n" ::"r"(s), "l"(gmem_ptr));
}
__device__ __forceinline__ void cp_commit() { asm volatile("cp.async.commit_group;\n"); }
template <int N>
__device__ __forceinline__ void cp_wait() {
    asm volatile("cp.async.wait_group %0;\n" ::"n"(N));
}

// C[e,m,n] = sum_k A[e,m,k] * B[e,n,k]  (NT)
// MODE 0: store raw accumulator           (gate -> scratch)
// MODE 1: out = silu(Gpre)*acc            (up, fused SwiGLU -> scratch in place)
// MODE 2: store raw accumulator           (down -> d_out)
template <int MODE>
__global__ void __launch_bounds__(THREADS)
gemm_nt(const float* __restrict__ A, const float* __restrict__ B,
        const float* __restrict__ Gpre, float* __restrict__ Cout,
        int N, int K, long strideA, long strideB, long strideC) {
    extern __shared__ float smem[];

    const int e = blockIdx.z;
    const float* Ae = A + (long)e * strideA;
    const float* Be = B + (long)e * strideB;

    const int bm = blockIdx.y, bn = blockIdx.x;
    const int tid = threadIdx.x;
    const int warp = tid >> 5, lane = tid & 31;
    const int wm = warp >> 1, wn = warp & 1;      // 2x2 warps, each 64x64
    const int gid = lane >> 2, tig = lane & 3;

    const int lrow = tid >> 3;          // 0..15
    const int lcol = (tid & 7) * 4;

    const float* Ag = Ae + (long)(bm * BM + lrow) * K + lcol;
    const float* Bg = Be + (long)(bn * BN + lrow) * K + lcol;

    float acc[4][8][4];
#pragma unroll
    for (int mt = 0; mt < 4; mt++)
#pragma unroll
        for (int nt = 0; nt < 8; nt++)
#pragma unroll
            for (int r = 0; r < 4; r++) acc[mt][nt][r] = 0.f;

    const int KT = K / BK;

    auto load_stage = [&](int kt) {
        float* as = smem + (kt & 1) * STAGE_F;
        float* bs = as + BM * LDSW;
        const long ko = (long)kt * BK;
#pragma unroll
        for (int i = 0; i < 8; i++) {
            cp_async16(&as[(lrow + i * 16) * LDSW + lcol], Ag + (long)(i * 16) * K + ko);
            cp_async16(&bs[(lrow + i * 16) * LDSW + lcol], Bg + (long)(i * 16) * K + ko);
        }
        cp_commit();
    };

    load_stage(0);

    for (int kt = 0; kt < KT; ++kt) {
        cp_wait<0>();          // stage kt arrived (sole pending group)
        __syncthreads();       // + all warps finished slot (kt+1)&1 in iter kt-1
        if (kt + 1 < KT) load_stage(kt + 1);   // safe: that slot is now free

        const float* as = smem + (kt & 1) * STAGE_F;
        const float* bs = as + BM * LDSW;

#pragma unroll
        for (int k8 = 0; k8 < BK / 8; k8++) {
            const int kc = k8 * 8;
            uint32_t afr[4][4];
            uint32_t bfr[8][2];
#pragma unroll
            for (int mt = 0; mt < 4; mt++) {
                const int r = wm * 64 + mt * 16 + gid;
                afr[mt][0] = f2tf32(as[r * LDSW + kc + tig]);
                afr[mt][1] = f2tf32(as[(r + 8) * LDSW + kc + tig]);
                afr[mt][2] = f2tf32(as[r * LDSW + kc + tig + 4]);
                afr[mt][3] = f2tf32(as[(r + 8) * LDSW + kc + tig + 4]);
            }
#pragma unroll
            for (int nt = 0; nt < 8; nt++) {
                const int c = wn * 64 + nt * 8 + gid;
                bfr[nt][0] = f2tf32(bs[c * LDSW + kc + tig]);
                bfr[nt][1] = f2tf32(bs[c * LDSW + kc + tig + 4]);
            }
#pragma unroll
            for (int mt = 0; mt < 4; mt++)
#pragma unroll
                for (int nt = 0; nt < 8; nt++) mma_tf32(acc[mt][nt], afr[mt], bfr[nt]);
        }
    }

    // epilogue
    const long base = (long)e * strideC;
#pragma unroll
    for (int mt = 0; mt < 4; mt++) {
#pragma unroll
        for (int nt = 0; nt < 8; nt++) {
            const int row0 = bm * BM + wm * 64 + mt * 16 + gid;
            const int col = bn * BN + wn * 64 + nt * 8 + tig * 2;
            const long i0 = base + (long)row0 * N + col;
            const long i1 = base + (long)(row0 + 8) * N + col;
            float2 v01 = make_float2(acc[mt][nt][0], acc[mt][nt][1]);
            float2 v23 = make_float2(acc[mt][nt][2], acc[mt][nt][3]);
            if (MODE == 1) {
                const float2 g0 = *reinterpret_cast<const float2*>(Gpre + i0);
                const float2 g1 = *reinterpret_cast<const float2*>(Gpre + i1);
                v01.x *= g0.x / (1.f + __expf(-g0.x));
                v01.y *= g0.y / (1.f + __expf(-g0.y));
                v23.x *= g1.x / (1.f + __expf(-g1.x));
                v23.y *= g1.y / (1.f + __expf(-g1.y));
            }
            *reinterpret_cast<float2*>(Cout + i0) = v01;
            *reinterpret_cast<float2*>(Cout + i1) = v23;
        }
    }
}

extern "C" void kernel_launch(void* const* d_in, const int* in_sizes, int n_in,
                              void* d_out, int out_size) {
    const float* x    = (const float*)d_in[0];  // [E, C, H]
    const float* gate = (const float*)d_in[1];  // [E, I, H]
    const float* up   = (const float*)d_in[2];  // [E, I, H]
    const float* down = (const float*)d_in[3];  // [E, H, I]
    float* out = (float*)d_out;                 // [E, C, H]

    float* scratch = nullptr;
    cudaGetSymbolAddress((void**)&scratch, g_scratch);

    cudaFuncSetAttribute(gemm_nt<0>, cudaFuncAttributeMaxDynamicSharedMemorySize, SMEM_BYTES);
    cudaFuncSetAttribute(gemm_nt<1>, cudaFuncAttributeMaxDynamicSharedMemorySize, SMEM_BYTES);
    cudaFuncSetAttribute(gemm_nt<2>, cudaFuncAttributeMaxDynamicSharedMemorySize, SMEM_BYTES);

    dim3 blk(THREADS);

    // 1) gate = X · Gateᵀ  -> scratch [E, C, I]
    gemm_nt<0><<<dim3(I_ / BN, C_ / BM, E_), blk, SMEM_BYTES>>>(
        x, gate, nullptr, scratch, I_, H_,
        (long)C_ * H_, (long)I_ * H_, (long)C_ * I_);

    // 2) inter = silu(gate) * (X · Upᵀ) -> scratch (in place)
    gemm_nt<1><<<dim3(I_ / BN, C_ / BM, E_), blk, SMEM_BYTES>>>(
        x, up, scratch, scratch, I_, H_,
        (long)C_ * H_, (long)I_ * H_, (long)C_ * I_);

    // 3) out = inter · Downᵀ  [E, C, H]
    gemm_nt<2><<<dim3(H_ / BN, C_ / BM, E_), blk, SMEM_BYTES>>>(
        scratch, down, nullptr, out, H_, I_,
        (long)C_ * I_, (long)H_ * I_, (long)C_ * H_);
}

// round 9
// speedup vs baseline: 1.0523x; 1.0125x over previous
#include <cuda_runtime.h>
#include <cstdint>
#include <math.h>

#define E_ 8
#define C_ 1024
#define H_ 2048
#define I_ 5632

// inter scratch [E, C, I] fp32 (176 MB)
__device__ float g_scratch[(size_t)E_ * C_ * I_];

constexpr int LDSW = 36;      // padded row stride (floats)
constexpr int THREADS = 128;  // 4 warps
constexpr int BK = 32;
constexpr int STAGE_F = 256 * LDSW;           // 9216 floats per stage (both kernels)
constexpr int SMEM_BYTES = 2 * STAGE_F * 4;   // 73728 B -> 3 CTAs/SM

__device__ __forceinline__ uint32_t f2tf32(float x) {
    uint32_t y;
    asm("cvt.rna.tf32.f32 %0, %1;" : "=r"(y) : "f"(x));
    return y;
}
__device__ __forceinline__ void mma_tf32(float (&c)[4], const uint32_t (&a)[4],
                                         const uint32_t (&b)[2]) {
    asm volatile(
        "mma.sync.aligned.m16n8k8.row.col.f32.tf32.tf32.f32 "
        "{%0,%1,%2,%3}, {%4,%5,%6,%7}, {%8,%9}, {%0,%1,%2,%3};\n"
        : "+f"(c[0]), "+f"(c[1]), "+f"(c[2]), "+f"(c[3])
        : "r"(a[0]), "r"(a[1]), "r"(a[2]), "r"(a[3]), "r"(b[0]), "r"(b[1]));
}
__device__ __forceinline__ void cp_async16(void* smem_ptr, const void* gmem_ptr) {
    uint32_t s = (uint32_t)__cvta_generic_to_shared(smem_ptr);
    asm volatile("cp.async.cg.shared.global [%0], [%1], 16;\n" ::"r"(s), "l"(gmem_ptr));
}
__device__ __forceinline__ void cp_commit() { asm volatile("cp.async.commit_group;\n"); }
template <int N>
__device__ __forceinline__ void cp_wait() {
    asm volatile("cp.async.wait_group %0;\n" ::"n"(N));
}
__device__ __forceinline__ float silu(float x) { return x / (1.f + __expf(-x)); }

// ====== fused gate+up: warps 0-1 -> G(128x64), warps 2-3 -> U(128x64) ======
// Stage rows: A[0:128], Bg[128:192], Bu[192:256]. Mainloop per warp == R6.
__global__ void __launch_bounds__(THREADS)
gateup_fused(const float* __restrict__ A, const float* __restrict__ Bg,
             const float* __restrict__ Bu, float* __restrict__ Cout) {
    extern __shared__ float smem[];
    constexpr int K = H_, N = I_, KT = K / BK;
    const int e = blockIdx.z;
    const int bm = blockIdx.y, bn = blockIdx.x;   // bn over I/64
    const int tid = threadIdx.x;
    const int warp = tid >> 5, lane = tid & 31;
    const bool is_g = warp < 2;
    const int wm = warp & 1;                      // 2 warps stacked in M per matrix
    const int gid = lane >> 2, tig = lane & 3;

    const int lrow = tid >> 3;   // 0..15
    const int lcol = (tid & 7) * 4;

    const float* Ag  = A  + (size_t)e * C_ * K + (size_t)(bm * 128 + lrow) * K + lcol;
    const float* Bgg = Bg + (size_t)e * I_ * K + (size_t)(bn * 64 + lrow) * K + lcol;
    const float* Bug = Bu + (size_t)e * I_ * K + (size_t)(bn * 64 + lrow) * K + lcol;

    float acc[4][8][4];
#pragma unroll
    for (int mt = 0; mt < 4; mt++)
#pragma unroll
        for (int nt = 0; nt < 8; nt++)
#pragma unroll
            for (int r = 0; r < 4; r++) acc[mt][nt][r] = 0.f;

    auto load_stage = [&](int kt) {
        float* st = smem + (kt & 1) * STAGE_F;
        const size_t ko = (size_t)kt * BK;
#pragma unroll
        for (int i = 0; i < 8; i++)
            cp_async16(&st[(lrow + i * 16) * LDSW + lcol], Ag + (size_t)(i * 16) * K + ko);
#pragma unroll
        for (int i = 0; i < 4; i++)
            cp_async16(&st[(128 + lrow + i * 16) * LDSW + lcol], Bgg + (size_t)(i * 16) * K + ko);
#pragma unroll
        for (int i = 0; i < 4; i++)
            cp_async16(&st[(192 + lrow + i * 16) * LDSW + lcol], Bug + (size_t)(i * 16) * K + ko);
    };

    load_stage(0); cp_commit();

    const int brow = is_g ? 128 : 192;
    for (int kt = 0; kt < KT; ++kt) {
        if (kt + 1 < KT) load_stage(kt + 1);
        cp_commit();
        cp_wait<1>();
        __syncthreads();

        const float* as = smem + (kt & 1) * STAGE_F;
        const float* bs = as + brow * LDSW;

#pragma unroll
        for (int k8 = 0; k8 < BK / 8; k8++) {
            const int kc = k8 * 8;
            uint32_t afr[4][4], bfr[8][2];
#pragma unroll
            for (int mt = 0; mt < 4; mt++) {
                const int r = wm * 64 + mt * 16 + gid;
                afr[mt][0] = f2tf32(as[r * LDSW + kc + tig]);
                afr[mt][1] = f2tf32(as[(r + 8) * LDSW + kc + tig]);
                afr[mt][2] = f2tf32(as[r * LDSW + kc + tig + 4]);
                afr[mt][3] = f2tf32(as[(r + 8) * LDSW + kc + tig + 4]);
            }
#pragma unroll
            for (int nt = 0; nt < 8; nt++) {
                const int c = nt * 8 + gid;
                bfr[nt][0] = f2tf32(bs[c * LDSW + kc + tig]);
                bfr[nt][1] = f2tf32(bs[c * LDSW + kc + tig + 4]);
            }
#pragma unroll
            for (int mt = 0; mt < 4; mt++)
#pragma unroll
                for (int nt = 0; nt < 8; nt++) mma_tf32(acc[mt][nt], afr[mt], bfr[nt]);
        }
        __syncthreads();
    }

    // ---- epilogue: U warps park acc in smem; G warps combine + store ----
    constexpr int UW = 68;   // 64 + 4 pad
    float* ux = smem;        // 128 x 68 floats = 34.8 KB (pipeline buffer reused)
    if (!is_g) {
#pragma unroll
        for (int mt = 0; mt < 4; mt++)
#pragma unroll
            for (int nt = 0; nt < 8; nt++) {
                const int r0 = wm * 64 + mt * 16 + gid;
                const int c = nt * 8 + tig * 2;
                *reinterpret_cast<float2*>(&ux[r0 * UW + c]) =
                    make_float2(acc[mt][nt][0], acc[mt][nt][1]);
                *reinterpret_cast<float2*>(&ux[(r0 + 8) * UW + c]) =
                    make_float2(acc[mt][nt][2], acc[mt][nt][3]);
            }
    }
    __syncthreads();
    if (is_g) {
        const size_t base = (size_t)e * C_ * N;
#pragma unroll
        for (int mt = 0; mt < 4; mt++)
#pragma unroll
            for (int nt = 0; nt < 8; nt++) {
                const int r0 = wm * 64 + mt * 16 + gid;
                const int c = nt * 8 + tig * 2;
                const float2 u0 = *reinterpret_cast<const float2*>(&ux[r0 * UW + c]);
                const float2 u1 = *reinterpret_cast<const float2*>(&ux[(r0 + 8) * UW + c]);
                const int grow = bm * 128 + r0;
                const int gcol = bn * 64 + c;
                const size_t i0 = base + (size_t)grow * N + gcol;
                const size_t i1 = base + (size_t)(grow + 8) * N + gcol;
                *reinterpret_cast<float2*>(Cout + i0) =
                    make_float2(silu(acc[mt][nt][0]) * u0.x, silu(acc[mt][nt][1]) * u0.y);
                *reinterpret_cast<float2*>(Cout + i1) =
                    make_float2(silu(acc[mt][nt][2]) * u1.x, silu(acc[mt][nt][3]) * u1.y);
            }
    }
}

// ====== down GEMM: out = inter · downᵀ (exact R6 mode-2) ======
__global__ void __launch_bounds__(THREADS)
down_gemm(const float* __restrict__ A, const float* __restrict__ B,
          float* __restrict__ Cout) {
    extern __shared__ float smem[];
    constexpr int K = I_, N = H_, KT = K / BK;
    const int e = blockIdx.z;
    const int bm = blockIdx.y, bn = blockIdx.x;
    const int tid = threadIdx.x;
    const int warp = tid >> 5, lane = tid & 31;
    const int wm = warp >> 1, wn = warp & 1;
    const int gid = lane >> 2, tig = lane & 3;

    const int lrow = tid >> 3;
    const int lcol = (tid & 7) * 4;

    const float* Ag = A + (size_t)e * C_ * K + (size_t)(bm * 128 + lrow) * K + lcol;
    const float* Bg = B + (size_t)e * H_ * K + (size_t)(bn * 128 + lrow) * K + lcol;

    float acc[4][8][4];
#pragma unroll
    for (int mt = 0; mt < 4; mt++)
#pragma unroll
        for (int nt = 0; nt < 8; nt++)
#pragma unroll
            for (int r = 0; r < 4; r++) acc[mt][nt][r] = 0.f;

    auto load_stage = [&](int kt) {
        float* as = smem + (kt & 1) * STAGE_F;
        float* bs = as + 128 * LDSW;
        const size_t ko = (size_t)kt * BK;
#pragma unroll
        for (int i = 0; i < 8; i++) {
            cp_async16(&as[(lrow + i * 16) * LDSW + lcol], Ag + (size_t)(i * 16) * K + ko);
            cp_async16(&bs[(lrow + i * 16) * LDSW + lcol], Bg + (size_t)(i * 16) * K + ko);
        }
    };

    load_stage(0); cp_commit();

    for (int kt = 0; kt < KT; ++kt) {
        if (kt + 1 < KT) load_stage(kt + 1);
        cp_commit();
        cp_wait<1>();
        __syncthreads();

        const float* as = smem + (kt & 1) * STAGE_F;
        const float* bs = as + 128 * LDSW;

#pragma unroll
        for (int k8 = 0; k8 < BK / 8; k8++) {
            const int kc = k8 * 8;
            uint32_t afr[4][4], bfr[8][2];
#pragma unroll
            for (int mt = 0; mt < 4; mt++) {
                const int r = wm * 64 + mt * 16 + gid;
                afr[mt][0] = f2tf32(as[r * LDSW + kc + tig]);
                afr[mt][1] = f2tf32(as[(r + 8) * LDSW + kc + tig]);
                afr[mt][2] = f2tf32(as[r * LDSW + kc + tig + 4]);
                afr[mt][3] = f2tf32(as[(r + 8) * LDSW + kc + tig + 4]);
            }
#pragma unroll
            for (int nt = 0; nt < 8; nt++) {
                const int c = wn * 64 + nt * 8 + gid;
                bfr[nt][0] = f2tf32(bs[c * LDSW + kc + tig]);
                bfr[nt][1] = f2tf32(bs[c * LDSW + kc + tig + 4]);
            }
#pragma unroll
            for (int mt = 0; mt < 4; mt++)
#pragma unroll
                for (int nt = 0; nt < 8; nt++) mma_tf32(acc[mt][nt], afr[mt], bfr[nt]);
        }
        __syncthreads();
    }

    const size_t base = (size_t)e * C_ * N;
#pragma unroll
    for (int mt = 0; mt < 4; mt++) {
#pragma unroll
        for (int nt = 0; nt < 8; nt++) {
            const int row0 = bm * 128 + wm * 64 + mt * 16 + gid;
            const int col = bn * 128 + wn * 64 + nt * 8 + tig * 2;
            const size_t i0 = base + (size_t)row0 * N + col;
            const size_t i1 = base + (size_t)(row0 + 8) * N + col;
            *reinterpret_cast<float2*>(Cout + i0) = make_float2(acc[mt][nt][0], acc[mt][nt][1]);
            *reinterpret_cast<float2*>(Cout + i1) = make_float2(acc[mt][nt][2], acc[mt][nt][3]);
        }
    }
}

extern "C" void kernel_launch(void* const* d_in, const int* in_sizes, int n_in,
                              void* d_out, int out_size) {
    const float* x    = (const float*)d_in[0];  // [E, C, H]
    const float* gate = (const float*)d_in[1];  // [E, I, H]
    const float* up   = (const float*)d_in[2];  // [E, I, H]
    const float* down = (const float*)d_in[3];  // [E, H, I]
    float* out = (float*)d_out;                 // [E, C, H]

    float* scratch = nullptr;
    cudaGetSymbolAddress((void**)&scratch, g_scratch);

    cudaFuncSetAttribute(gateup_fused, cudaFuncAttributeMaxDynamicSharedMemorySize, SMEM_BYTES);
    cudaFuncSetAttribute(down_gemm, cudaFuncAttributeMaxDynamicSharedMemorySize, SMEM_BYTES);

    // 1) inter = silu(X·gateᵀ) * (X·upᵀ) -> scratch [E, C, I]
    gateup_fused<<<dim3(I_ / 64, C_ / 128, E_), THREADS, SMEM_BYTES>>>(x, gate, up, scratch);
    // 2) out = inter · downᵀ [E, C, H]
    down_gemm<<<dim3(H_ / 128, C_ / 128, E_), THREADS, SMEM_BYTES>>>(scratch, down, out);
}